// round 12
// baseline (speedup 1.0000x reference)
#include <cuda_runtime.h>
#include <math.h>
#include <stdint.h>

// ---------------- problem constants ----------------
#define BNODES   4096      // B*N
#define HDIM     256
#define EMAX     16384

// rounded-weight buffer offsets (floats)
#define OFF_IN   0                    // 192*256
#define OFF_MSG  49152                // 256*256
#define OFF_UPD  114688               // 512*256
#define OFF_ADD  245760               // (layout spacer)
#define OFF_W1   311296               // (layout spacer)
#define OFF_W2   442368               // 256*256
#define WR_TOTAL 507904
#define RW_BLOCKS ((WR_TOTAL/4 + 255)/256)   // 496

// ---------------- scratch (device globals, no allocs) ----------------
__device__ float g_h   [BNODES*HDIM];
__device__ float g_ht  [BNODES*HDIM];
__device__ float g_Hm  [BNODES*HDIM];
__device__ float g_P   [BNODES*HDIM];
__device__ float g_agg [BNODES*HDIM];
__device__ float g_A   [BNODES*HDIM];
__device__ float g_B   [BNODES*HDIM];
__device__ float g_Wr  [WR_TOTAL];
__device__ float g_WAB [2*HDIM*HDIM];  // WA=Wadd_top@W1top, WB=Wadd_top@W1bot (tf32-rounded)
__device__ float g_pa  [64*HDIM];      // propadd@W1top + b1
__device__ float g_pb  [64*HDIM];      // propadd@W1bot
__device__ float g_WfoldT[5*HDIM];     // [c][k]
__device__ float g_bfold[8];
__device__ double g_acc;

// ---------------- helpers ----------------
__device__ __forceinline__ uint32_t f2tf32(float x) {
    uint32_t r;
    asm("cvt.rna.tf32.f32 %0, %1;" : "=r"(r) : "f"(x));
    return r;
}
__device__ __forceinline__ float roundtf(float x) { return __uint_as_float(f2tf32(x)); }

__device__ __forceinline__ void mma_tf32(float& d0, float& d1, float& d2, float& d3,
                                         uint32_t a0, uint32_t a1, uint32_t a2, uint32_t a3,
                                         uint32_t b0, uint32_t b1)
{
    asm volatile(
        "mma.sync.aligned.m16n8k8.row.col.f32.tf32.tf32.f32 "
        "{%0,%1,%2,%3}, {%4,%5,%6,%7}, {%8,%9}, {%0,%1,%2,%3};"
        : "+f"(d0), "+f"(d1), "+f"(d2), "+f"(d3)
        : "r"(a0), "r"(a1), "r"(a2), "r"(a3), "r"(b0), "r"(b1));
}

__device__ __forceinline__ void cp_async16(void* smem_ptr, const void* gmem_ptr)
{
    uint32_t s = (uint32_t)__cvta_generic_to_shared(smem_ptr);
    asm volatile("cp.async.cg.shared.global [%0], [%1], 16;" :: "r"(s), "l"(gmem_ptr));
}
__device__ __forceinline__ void cp_commit() { asm volatile("cp.async.commit_group;"); }
template<int N> __device__ __forceinline__ void cp_wait() {
    asm volatile("cp.async.wait_group %0;" :: "n"(N));
}

// ---------------- setup: folds + pa/pb + WA/WB + weight rounding, one kernel --------
__global__ void __launch_bounds__(256)
setup_kernel(const float* __restrict__ W3, const float* __restrict__ b3,
             const float* __restrict__ W_out, const float* __restrict__ b_out,
             const float* __restrict__ props, const float* __restrict__ W_prop,
             const float* __restrict__ b_prop, const float* __restrict__ W_add,
             const float* __restrict__ b_add, const float* __restrict__ b1,
             const float* __restrict__ W_in, const float* __restrict__ W_msg,
             const float* __restrict__ W_upd, const float* __restrict__ W1,
             const float* __restrict__ W2)
{
    int bid = blockIdx.x;
    int tid = threadIdx.x;
    if (bid >= 201) {
        int i = ((bid - 201) * 256 + tid) * 4;
        if (i >= WR_TOTAL) return;
        const float* src;
        int off;
        if      (i < OFF_MSG) { src = W_in;  off = OFF_IN;  }
        else if (i < OFF_UPD) { src = W_msg; off = OFF_MSG; }
        else if (i < OFF_ADD) { src = W_upd; off = OFF_UPD; }
        else if (i < OFF_W1)  { src = W_add; off = OFF_ADD; }
        else if (i < OFF_W2)  { src = W1;    off = OFF_W1;  }
        else                  { src = W2;    off = OFF_W2;  }
        float4 v = *(const float4*)&src[i - off];
        v.x = roundtf(v.x); v.y = roundtf(v.y); v.z = roundtf(v.z); v.w = roundtf(v.w);
        *(float4*)&g_Wr[i] = v;
    } else if (bid < 64) {
        // pa[b][n] = b1[n] + propadd[b] @ W1top[:,n] ; pb[b][n] = propadd[b] @ W1bot[:,n]
        __shared__ float pe[64];
        __shared__ float padd[256];
        if (tid < 64) pe[tid] = props[bid] * W_prop[tid] + b_prop[tid];
        __syncthreads();
        {
            float s = b_add[tid];
            #pragma unroll 8
            for (int p = 0; p < 64; p++) s += pe[p] * W_add[(256 + p)*256 + tid];
            padd[tid] = s;
        }
        __syncthreads();
        float a = b1[tid], b = 0.f;
        for (int t = 0; t < 256; t++) {
            float pv = padd[t];
            a += pv * W1[(size_t)t*256 + tid];
            b += pv * W1[(size_t)(256 + t)*256 + tid];
        }
        g_pa[bid*256 + tid] = a;
        g_pb[bid*256 + tid] = b;
    } else if (bid < 72) {
        int t = (bid - 64)*32 + (tid >> 3);
        int l = tid & 7;
        float s[5] = {0.f,0.f,0.f,0.f,0.f};
        for (int j = l; j < 512; j += 8) {
            float w3 = W3[t*512 + j];
            #pragma unroll
            for (int c = 0; c < 5; c++) s[c] += w3 * W_out[j*5 + c];
        }
        #pragma unroll
        for (int off = 4; off; off >>= 1)
            #pragma unroll
            for (int c = 0; c < 5; c++) s[c] += __shfl_down_sync(0xffffffffu, s[c], off, 8);
        if (l == 0) {
            #pragma unroll
            for (int c = 0; c < 5; c++) g_WfoldT[c*256 + t] = s[c];
        }
    } else if (bid == 72) {
        if (tid < 5) {
            float s = b_out[tid];
            for (int k = 0; k < 512; k++) s += b3[k] * W_out[k*5 + tid];
            g_bfold[tid] = s;
        }
        if (tid == 32) g_acc = 0.0;
    } else {
        // WA/WB: WX[k][n] = sum_t W_add[k][t] * W1half[t][n], tf32-rounded
        int q = bid - 73;            // 0..127
        int isB = q >= 64;
        int k0 = (q & 63) * 4;
        const float* W1p = W1 + (isB ? 256*256 : 0);
        float s0 = 0.f, s1 = 0.f, s2 = 0.f, s3 = 0.f;
        for (int t = 0; t < 256; t++) {
            float w = W1p[(size_t)t*256 + tid];
            s0 += W_add[(k0+0)*256 + t] * w;
            s1 += W_add[(k0+1)*256 + t] * w;
            s2 += W_add[(k0+2)*256 + t] * w;
            s3 += W_add[(k0+3)*256 + t] * w;
        }
        float* dstp = g_WAB + (size_t)isB*65536 + (size_t)k0*256;
        dstp[0*256 + tid] = roundtf(s0);
        dstp[1*256 + tid] = roundtf(s1);
        dstp[2*256 + tid] = roundtf(s2);
        dstp[3*256 + tid] = roundtf(s3);
    }
}

// ---------------- edge scatter (32 edges/block, unroll 8) ----------------
__global__ void __launch_bounds__(256)
edge_scatter(const int* __restrict__ src, const int* __restrict__ dst,
             const float* __restrict__ ea, const float* __restrict__ W_msg,
             const float* __restrict__ b_msg, const float* __restrict__ Hm,
             float* __restrict__ agg, int E)
{
    __shared__ float We[5][256];
    __shared__ float bm[256];
    __shared__ float eas[32][5];
    __shared__ int   ss[32], ds[32];
    int tid = threadIdx.x;
    const float* Wep = W_msg + 256*256;
    for (int i = tid; i < 5*256; i += 256) ((float*)We)[i] = Wep[i];
    bm[tid] = b_msg[tid];
    int e0 = blockIdx.x * 32;
    if (tid < 32 && e0 + tid < E) { ss[tid] = src[e0+tid]; ds[tid] = dst[e0+tid]; }
    if (tid >= 64 && tid < 64 + 160) {
        int i = tid - 64;
        if ((size_t)e0*5 + i < (size_t)E*5) eas[i/5][i%5] = ea[(size_t)e0*5 + i];
    }
    __syncthreads();
    #pragma unroll 8
    for (int q = 0; q < 32; q++) {
        int e = e0 + q;
        if (e >= E) break;
        float v = bm[tid]
                + eas[q][0]*We[0][tid] + eas[q][1]*We[1][tid] + eas[q][2]*We[2][tid]
                + eas[q][3]*We[3][tid] + eas[q][4]*We[4][tid]
                + Hm[(size_t)ss[q]*256 + tid];
        v = fmaxf(v, 0.f);
        atomicAdd(&agg[(size_t)ds[q]*256 + tid], v);
    }
}

// ---------------- tf32 tensor-core SGEMM (R8 2-stage pipeline + dual flags + addBuf) --
#define APAD 68
#define WPAD 72
template<int CVTA, int CVTA2>
__global__ void __launch_bounds__(256)
sgemm_tc(const float* __restrict__ A1, const float* __restrict__ W1, int K1,
         const float* __restrict__ A2, const float* __restrict__ W2, int K2,
         const float* bias, const float* rowBias,
         float* C, int doRelu, int doRound,
         const float* __restrict__ Wd, float* Cd, int dualSplit,
         float* __restrict__ zeroBuf, const float* rowBiasD,
         const float* biasD, int doReluD, int doRoundD,
         const float* __restrict__ addBuf)
{
    extern __shared__ float sm[];
    float* Asm = sm;                   // [2][64][APAD]
    float* Wsm = sm + 2*64*APAD;       // [2][64][WPAD]

    int tid = threadIdx.x;
    int wid = tid >> 5;
    int lane = tid & 31;
    int warp_m = wid & 1;
    int warp_n = wid >> 1;
    int gi = lane >> 2;
    int tg = lane & 3;

    int m0 = blockIdx.y * 64;
    int n0;
    const float* PW1 = W1;
    if (dualSplit && (int)blockIdx.x >= dualSplit) {
        PW1 = Wd; C = Cd; bias = biasD; rowBias = rowBiasD;
        doRelu = doReluD; doRound = doRoundD; zeroBuf = nullptr;
        n0 = ((int)blockIdx.x - dualSplit) * 64;
    } else {
        n0 = blockIdx.x * 64;
    }

    float acc[2][2][4];
    #pragma unroll
    for (int mt = 0; mt < 2; mt++)
        #pragma unroll
        for (int nt = 0; nt < 2; nt++)
            #pragma unroll
            for (int q = 0; q < 4; q++) acc[mt][nt][q] = 0.f;

    int lr[4], lc[4];
    #pragma unroll
    for (int i = 0; i < 4; i++) { int f = tid + i*256; lr[i] = f >> 4; lc[i] = (f & 15) * 4; }

    for (int pass = 0; pass < 2; pass++) {
        const float* A = pass ? A2 : A1;
        const float* W = pass ? W2 : PW1;
        int K = pass ? K2 : K1;
        if (K == 0) break;
        int nit = K >> 6;
        int cvtA = pass ? CVTA2 : CVTA;

        #pragma unroll
        for (int i = 0; i < 4; i++) {
            cp_async16(&Asm[0*64*APAD + lr[i]*APAD + lc[i]],
                       &A[(size_t)(m0 + lr[i])*K + lc[i]]);
            cp_async16(&Wsm[0*64*WPAD + lr[i]*WPAD + lc[i]],
                       &W[(size_t)lr[i]*256 + n0 + lc[i]]);
        }
        cp_commit();

        for (int it = 0; it < nit; it++) {
            int cur = it & 1;
            if (it + 1 < nit) {
                int nb = cur ^ 1;
                int k0n = (it + 1) << 6;
                #pragma unroll
                for (int i = 0; i < 4; i++) {
                    cp_async16(&Asm[nb*64*APAD + lr[i]*APAD + lc[i]],
                               &A[(size_t)(m0 + lr[i])*K + k0n + lc[i]]);
                    cp_async16(&Wsm[nb*64*WPAD + lr[i]*WPAD + lc[i]],
                               &W[(size_t)(k0n + lr[i])*256 + n0 + lc[i]]);
                }
                cp_commit();
                cp_wait<1>();
            } else {
                cp_wait<0>();
            }
            __syncthreads();

            const float* Ab = Asm + cur*64*APAD;
            const float* Wb = Wsm + cur*64*WPAD;
            #pragma unroll
            for (int kb = 0; kb < 8; kb++) {
                int k8 = kb*8;
                uint32_t a[2][4];
                #pragma unroll
                for (int mt = 0; mt < 2; mt++) {
                    int m = warp_m*32 + mt*16 + gi;
                    if (cvtA) {
                        a[mt][0] = f2tf32(Ab[(m    )*APAD + k8 + tg    ]);
                        a[mt][1] = f2tf32(Ab[(m + 8)*APAD + k8 + tg    ]);
                        a[mt][2] = f2tf32(Ab[(m    )*APAD + k8 + tg + 4]);
                        a[mt][3] = f2tf32(Ab[(m + 8)*APAD + k8 + tg + 4]);
                    } else {
                        a[mt][0] = __float_as_uint(Ab[(m    )*APAD + k8 + tg    ]);
                        a[mt][1] = __float_as_uint(Ab[(m + 8)*APAD + k8 + tg    ]);
                        a[mt][2] = __float_as_uint(Ab[(m    )*APAD + k8 + tg + 4]);
                        a[mt][3] = __float_as_uint(Ab[(m + 8)*APAD + k8 + tg + 4]);
                    }
                }
                #pragma unroll
                for (int nt = 0; nt < 2; nt++) {
                    int n = warp_n*16 + nt*8 + gi;
                    uint32_t b0 = __float_as_uint(Wb[(k8 + tg    )*WPAD + n]);
                    uint32_t b1 = __float_as_uint(Wb[(k8 + tg + 4)*WPAD + n]);
                    #pragma unroll
                    for (int mt = 0; mt < 2; mt++)
                        mma_tf32(acc[mt][nt][0], acc[mt][nt][1], acc[mt][nt][2], acc[mt][nt][3],
                                 a[mt][0], a[mt][1], a[mt][2], a[mt][3], b0, b1);
                }
            }
            __syncthreads();
        }
    }

    #pragma unroll
    for (int mt = 0; mt < 2; mt++) {
        #pragma unroll
        for (int half = 0; half < 2; half++) {
            int m = m0 + warp_m*32 + mt*16 + gi + half*8;
            #pragma unroll
            for (int nt = 0; nt < 2; nt++) {
                int n = n0 + warp_n*16 + nt*8 + tg*2;
                float v0 = acc[mt][nt][half*2 + 0];
                float v1 = acc[mt][nt][half*2 + 1];
                if (bias)    { v0 += bias[n]; v1 += bias[n+1]; }
                if (rowBias) {
                    const float* rb = rowBias + ((m >> 6) << 8);
                    v0 += rb[n]; v1 += rb[n+1];
                }
                if (addBuf) {
                    v0 += addBuf[(size_t)m*256 + n];
                    v1 += addBuf[(size_t)m*256 + n + 1];
                }
                if (doRelu)  { v0 = fmaxf(v0, 0.f); v1 = fmaxf(v1, 0.f); }
                if (doRound) { v0 = roundtf(v0); v1 = roundtf(v1); }
                *(float2*)&C[(size_t)m*256 + n] = make_float2(v0, v1);
                if (zeroBuf) *(float2*)&zeroBuf[(size_t)m*256 + n] = make_float2(0.f, 0.f);
            }
        }
    }
}

// ---------------- pair megakernel (R8 config) ----------------
__global__ void __launch_bounds__(512, 1)
pair_kernel(const float* __restrict__ Ag, const float* __restrict__ Bg,
            const int* __restrict__ sel_b, const int* __restrict__ sel_i,
            const int* __restrict__ sel_j, const int* __restrict__ golden,
            const float* __restrict__ W2r, const float* __restrict__ b2)
{
    extern __shared__ uint32_t smem[];
    uint32_t* h1u = smem;                    // [128][260] tf32, reused as fp32 h2
    uint32_t* w2u = h1u + 128*260;           // [2][32][260] tf32 bits (double buffer)
    float*    wfs = (float*)(w2u + 2*32*260);// [5][256]
    float*    b2s = wfs + 5*256;             // [256]
    float*    bfs = b2s + 256;               // [8]
    float*    h1f = (float*)h1u;
    float*    w2f = (float*)w2u;

    int tid  = threadIdx.x;
    int wid  = tid >> 5;
    int lane = tid & 31;
    int warp_m = wid & 3;
    int warp_n = wid >> 2;
    int gi = lane >> 2;
    int tg = lane & 3;
    int e0 = blockIdx.x * 128;

    int w_k[4], w_nq[4];
    #pragma unroll
    for (int i = 0; i < 4; i++) { int f = tid + i*512; w_k[i] = f >> 6; w_nq[i] = (f & 63) * 4; }

    #pragma unroll
    for (int i = 0; i < 4; i++)
        cp_async16(&w2f[0*32*260 + w_k[i]*260 + w_nq[i]],
                   &W2r[(size_t)w_k[i]*256 + w_nq[i]]);
    cp_commit();

    for (int i = tid; i < 5*256; i += 512) wfs[i] = g_WfoldT[i];
    if (tid < 256) b2s[tid] = b2[tid];
    if (tid < 5) bfs[tid] = g_bfold[tid];

    // gather: h1 = relu(A[bi*64+si] + B[bi*64+sj])
    #pragma unroll
    for (int t = 0; t < 8; t++) {
        int r = wid*8 + t;
        int e = e0 + r;
        int bsel = sel_b[e];
        int ii = bsel*64 + sel_i[e];
        int jj = bsel*64 + sel_j[e];
        const float* ap = Ag + (size_t)ii*256;
        const float* bp = Bg + (size_t)jj*256;
        #pragma unroll
        for (int q = 0; q < 2; q++) {
            int c = lane*4 + q*128;
            float4 av = *(const float4*)(ap + c);
            float4 bv = *(const float4*)(bp + c);
            h1u[r*260 + c + 0] = f2tf32(fmaxf(av.x + bv.x, 0.f));
            h1u[r*260 + c + 1] = f2tf32(fmaxf(av.y + bv.y, 0.f));
            h1u[r*260 + c + 2] = f2tf32(fmaxf(av.z + bv.z, 0.f));
            h1u[r*260 + c + 3] = f2tf32(fmaxf(av.w + bv.w, 0.f));
        }
    }

    float acc[2][8][4];
    #pragma unroll
    for (int mt = 0; mt < 2; mt++)
        #pragma unroll
        for (int nt = 0; nt < 8; nt++)
            #pragma unroll
            for (int q = 0; q < 4; q++) acc[mt][nt][q] = 0.f;

    for (int kc = 0; kc < 8; kc++) {
        int cur = kc & 1;
        if (kc + 1 < 8) {
            int nb = cur ^ 1;
            int k0n = (kc + 1) * 32;
            #pragma unroll
            for (int i = 0; i < 4; i++)
                cp_async16(&w2f[nb*32*260 + w_k[i]*260 + w_nq[i]],
                           &W2r[(size_t)(k0n + w_k[i])*256 + w_nq[i]]);
            cp_commit();
            cp_wait<1>();
        } else {
            cp_wait<0>();
        }
        __syncthreads();

        int k0 = kc * 32;
        const uint32_t* wb = w2u + cur*32*260;
        #pragma unroll
        for (int ks = 0; ks < 4; ks++) {
            int kb = ks*8;
            uint32_t a[2][4];
            #pragma unroll
            for (int mt = 0; mt < 2; mt++) {
                int m = warp_m*32 + mt*16 + gi;
                a[mt][0] = h1u[(m    )*260 + k0 + kb + tg    ];
                a[mt][1] = h1u[(m + 8)*260 + k0 + kb + tg    ];
                a[mt][2] = h1u[(m    )*260 + k0 + kb + tg + 4];
                a[mt][3] = h1u[(m + 8)*260 + k0 + kb + tg + 4];
            }
            #pragma unroll
            for (int nt = 0; nt < 8; nt++) {
                int n = warp_n*64 + nt*8 + gi;
                uint32_t b0 = wb[(kb + tg    )*260 + n];
                uint32_t b1 = wb[(kb + tg + 4)*260 + n];
                #pragma unroll
                for (int mt = 0; mt < 2; mt++)
                    mma_tf32(acc[mt][nt][0], acc[mt][nt][1], acc[mt][nt][2], acc[mt][nt][3],
                             a[mt][0], a[mt][1], a[mt][2], a[mt][3], b0, b1);
            }
        }
        __syncthreads();
    }

    // h2 = relu(acc + b2)
    #pragma unroll
    for (int mt = 0; mt < 2; mt++) {
        #pragma unroll
        for (int half = 0; half < 2; half++) {
            int m = warp_m*32 + mt*16 + gi + half*8;
            #pragma unroll
            for (int nt = 0; nt < 8; nt++) {
                int n = warp_n*64 + nt*8 + tg*2;
                float v0 = fmaxf(acc[mt][nt][half*2 + 0] + b2s[n],     0.f);
                float v1 = fmaxf(acc[mt][nt][half*2 + 1] + b2s[n + 1], 0.f);
                h1f[m*260 + n]     = v0;
                h1f[m*260 + n + 1] = v1;
            }
        }
    }
    __syncthreads();

    // logits + loss
    double lsum = 0.0;
    for (int t = 0; t < 8; t++) {
        int r = wid*8 + t;
        float p[5] = {0.f,0.f,0.f,0.f,0.f};
        #pragma unroll
        for (int m8 = 0; m8 < 8; m8++) {
            int k = lane + 32*m8;
            float hv = h1f[r*260 + k];
            #pragma unroll
            for (int c = 0; c < 5; c++) p[c] += hv * wfs[c*256 + k];
        }
        #pragma unroll
        for (int off = 16; off; off >>= 1)
            #pragma unroll
            for (int c = 0; c < 5; c++) p[c] += __shfl_xor_sync(0xffffffffu, p[c], off);
        if (lane == 0) {
            float lg[5], mx = -1e30f;
            #pragma unroll
            for (int c = 0; c < 5; c++) { lg[c] = p[c] + bfs[c]; mx = fmaxf(mx, lg[c]); }
            float s = 0.f;
            #pragma unroll
            for (int c = 0; c < 5; c++) s += expf(lg[c] - mx);
            float lse = mx + logf(s);
            int gold = golden[e0 + r];
            lsum += (double)(lse - lg[gold]);
        }
    }
    if (lane == 0) atomicAdd(&g_acc, lsum);
}

// ---------------- finalize ----------------
__global__ void finalize_kernel(float* __restrict__ out, int esel)
{
    out[0] = (float)(g_acc / (double)esel);
}

// ---------------- host launcher ----------------
extern "C" void kernel_launch(void* const* d_in, const int* in_sizes, int n_in,
                              void* d_out, int out_size)
{
    const float* x         = (const float*)d_in[0];
    const int*   eidx      = (const int*)  d_in[1];
    const float* edge_attr = (const float*)d_in[2];
    const float* props     = (const float*)d_in[3];
    const int*   sel_b     = (const int*)  d_in[4];
    const int*   sel_i     = (const int*)  d_in[5];
    const int*   sel_j     = (const int*)  d_in[6];
    const int*   golden    = (const int*)  d_in[7];
    const float* W_prop = (const float*)d_in[8];
    const float* b_prop = (const float*)d_in[9];
    const float* W_in   = (const float*)d_in[10];
    const float* b_in   = (const float*)d_in[11];
    const float* W_msg  = (const float*)d_in[12];
    const float* b_msg  = (const float*)d_in[13];
    const float* W_upd  = (const float*)d_in[14];
    const float* b_upd  = (const float*)d_in[15];
    const float* W_add  = (const float*)d_in[16];
    const float* b_add  = (const float*)d_in[17];
    const float* W1     = (const float*)d_in[18];
    const float* b1     = (const float*)d_in[19];
    const float* W2     = (const float*)d_in[20];
    const float* b2     = (const float*)d_in[21];
    const float* W3     = (const float*)d_in[22];
    const float* b3     = (const float*)d_in[23];
    const float* W_out  = (const float*)d_in[24];
    const float* b_out  = (const float*)d_in[25];

    int E    = in_sizes[1] / 2;
    int ESEL = in_sizes[4];
    const int* src = eidx;
    const int* dst = eidx + E;

    float *p_h, *p_ht, *p_agg, *p_A, *p_B, *p_Hm, *p_P, *p_Wr, *p_WAB, *p_pa, *p_pb;
    cudaGetSymbolAddress((void**)&p_h,    g_h);
    cudaGetSymbolAddress((void**)&p_ht,   g_ht);
    cudaGetSymbolAddress((void**)&p_agg,  g_agg);
    cudaGetSymbolAddress((void**)&p_A,    g_A);
    cudaGetSymbolAddress((void**)&p_B,    g_B);
    cudaGetSymbolAddress((void**)&p_Hm,   g_Hm);
    cudaGetSymbolAddress((void**)&p_P,    g_P);
    cudaGetSymbolAddress((void**)&p_Wr,   g_Wr);
    cudaGetSymbolAddress((void**)&p_WAB,  g_WAB);
    cudaGetSymbolAddress((void**)&p_pa,   g_pa);
    cudaGetSymbolAddress((void**)&p_pb,   g_pb);

    int gemmSmem = (2*64*APAD + 2*64*WPAD) * (int)sizeof(float);
    cudaFuncSetAttribute((const void*)sgemm_tc<0,0>, cudaFuncAttributeMaxDynamicSharedMemorySize, gemmSmem);
    cudaFuncSetAttribute((const void*)sgemm_tc<1,0>, cudaFuncAttributeMaxDynamicSharedMemorySize, gemmSmem);
    int pairSmem = (128*260 + 2*32*260 + 5*256 + 256 + 8) * (int)sizeof(float);  // ~201 KB
    cudaFuncSetAttribute(pair_kernel, cudaFuncAttributeMaxDynamicSharedMemorySize, pairSmem);

    dim3 gemmGrid(4, BNODES/64);
    dim3 gemmGridDual(8, BNODES/64);

    const float* Wr_in  = p_Wr + OFF_IN;
    const float* Wr_msg = p_Wr + OFF_MSG;
    const float* Wr_upd = p_Wr + OFF_UPD;
    const float* Wr_w2  = p_Wr + OFF_W2;
    const float* WA_r   = p_WAB;
    const float* WB_r   = p_WAB + 65536;

    // ---- one-time setup ----
    setup_kernel<<<201 + RW_BLOCKS, 256>>>(W3, b3, W_out, b_out, props, W_prop, b_prop,
                                           W_add, b_add, b1, W_in, W_msg, W_upd, W1, W2);

    // h0 = relu(x @ W_in + b_in), rounded (x unrounded -> CVTA=1)
    sgemm_tc<1,0><<<gemmGrid, 256, gemmSmem>>>(x, Wr_in, 192, nullptr, nullptr, 0,
                                               b_in, nullptr, p_h, 1, 1,
                                               nullptr, nullptr, 0, nullptr, nullptr,
                                               nullptr, 0, 0, nullptr);

    float* cur = p_h;
    float* nxt = p_ht;
    for (int t = 0; t < 4; t++) {
        // dual: Hm = round(h@W_msg) [zeroes agg] ; P = h@W_upd_top + b_upd (fp32)
        sgemm_tc<0,0><<<gemmGridDual, 256, gemmSmem>>>(cur, Wr_msg, 256, nullptr, nullptr, 0,
                                                       nullptr, nullptr, p_Hm, 0, 1,
                                                       Wr_upd, p_P, 4, p_agg, nullptr,
                                                       b_upd, 0, 0, nullptr);
        // agg[dst] += relu(Hm[src] + b_msg + ea@We)
        edge_scatter<<<(E + 31)/32, 256>>>(src, dst, edge_attr, W_msg, b_msg, p_Hm, p_agg, E);
        // h' = relu(round(agg)@W_upd_bot + P), rounded  (K=256 only)
        sgemm_tc<1,0><<<gemmGrid, 256, gemmSmem>>>(p_agg, Wr_upd + 256*256, 256, nullptr, nullptr, 0,
                                                   nullptr, nullptr, nxt, 1, 1,
                                                   nullptr, nullptr, 0, nullptr, nullptr,
                                                   nullptr, 0, 0, p_P);
        float* tmp = cur; cur = nxt; nxt = tmp;
    }

    // A = h@WA + pa[batch] ; B = h@WB + pb[batch]  (embg folded; one dual launch)
    sgemm_tc<0,0><<<gemmGridDual, 256, gemmSmem>>>(cur, WA_r, 256, nullptr, nullptr, 0,
                                                   nullptr, p_pa, p_A, 0, 0,
                                                   WB_r, p_B, 4, nullptr, p_pb,
                                                   nullptr, 0, 0, nullptr);

    // pair stage + loss
    pair_kernel<<<ESEL/128, 512, pairSmem>>>(p_A, p_B, sel_b, sel_i, sel_j, golden, Wr_w2, b2);

    finalize_kernel<<<1, 1>>>((float*)d_out, ESEL);
}

// round 13
// speedup vs baseline: 1.1870x; 1.1870x over previous
#include <cuda_runtime.h>
#include <cuda_bf16.h>
#include <math.h>
#include <stdint.h>

// ---------------- problem constants ----------------
#define BNODES   4096      // B*N
#define HDIM     256
#define EMAX     16384

// rounded-weight buffer offsets (floats)
#define OFF_IN   0                    // 192*256
#define OFF_MSG  49152                // 256*256
#define OFF_UPD  114688               // 512*256
#define OFF_ADD  245760               // (spacer)
#define OFF_W1   311296               // (spacer)
#define OFF_W2   442368               // 256*256
#define WR_TOTAL 507904
#define RW_BLOCKS ((WR_TOTAL/4 + 255)/256)   // 496
#define W2T_BLK0 (201 + RW_BLOCKS)           // 697

// ---------------- scratch (device globals, no allocs) ----------------
__device__ float g_h   [BNODES*HDIM];
__device__ float g_ht  [BNODES*HDIM];
__device__ float g_Hm  [BNODES*HDIM];
__device__ float g_agg [BNODES*HDIM];
__device__ float g_A   [BNODES*HDIM];
__device__ float g_B   [BNODES*HDIM];
__device__ float g_Wr  [WR_TOTAL];
__device__ float g_WAB [2*HDIM*HDIM];  // WA, WB (tf32-rounded)
__device__ float g_pa  [64*HDIM];
__device__ float g_pb  [64*HDIM];
__device__ __nv_bfloat16 g_W2T[HDIM*HDIM];  // W2 transposed [n][k], bf16
__device__ float g_WfoldT[5*HDIM];
__device__ float g_bfold[8];
__device__ double g_acc;

// ---------------- helpers ----------------
__device__ __forceinline__ uint32_t f2tf32(float x) {
    uint32_t r;
    asm("cvt.rna.tf32.f32 %0, %1;" : "=r"(r) : "f"(x));
    return r;
}
__device__ __forceinline__ float roundtf(float x) { return __uint_as_float(f2tf32(x)); }

__device__ __forceinline__ uint32_t f2bf2(float lo, float hi) {
    uint32_t r;
    asm("cvt.rn.bf16x2.f32 %0, %1, %2;" : "=r"(r) : "f"(hi), "f"(lo));
    return r;
}

__device__ __forceinline__ void mma_tf32(float& d0, float& d1, float& d2, float& d3,
                                         uint32_t a0, uint32_t a1, uint32_t a2, uint32_t a3,
                                         uint32_t b0, uint32_t b1)
{
    asm volatile(
        "mma.sync.aligned.m16n8k8.row.col.f32.tf32.tf32.f32 "
        "{%0,%1,%2,%3}, {%4,%5,%6,%7}, {%8,%9}, {%0,%1,%2,%3};"
        : "+f"(d0), "+f"(d1), "+f"(d2), "+f"(d3)
        : "r"(a0), "r"(a1), "r"(a2), "r"(a3), "r"(b0), "r"(b1));
}

__device__ __forceinline__ void mma_bf16(float& d0, float& d1, float& d2, float& d3,
                                         uint32_t a0, uint32_t a1, uint32_t a2, uint32_t a3,
                                         uint32_t b0, uint32_t b1)
{
    asm volatile(
        "mma.sync.aligned.m16n8k16.row.col.f32.bf16.bf16.f32 "
        "{%0,%1,%2,%3}, {%4,%5,%6,%7}, {%8,%9}, {%0,%1,%2,%3};"
        : "+f"(d0), "+f"(d1), "+f"(d2), "+f"(d3)
        : "r"(a0), "r"(a1), "r"(a2), "r"(a3), "r"(b0), "r"(b1));
}

__device__ __forceinline__ void cp_async16(void* smem_ptr, const void* gmem_ptr)
{
    uint32_t s = (uint32_t)__cvta_generic_to_shared(smem_ptr);
    asm volatile("cp.async.cg.shared.global [%0], [%1], 16;" :: "r"(s), "l"(gmem_ptr));
}
__device__ __forceinline__ void cp_commit() { asm volatile("cp.async.commit_group;"); }
template<int N> __device__ __forceinline__ void cp_wait() {
    asm volatile("cp.async.wait_group %0;" :: "n"(N));
}

// ---------------- setup: folds + pa/pb + WA/WB + weight rounding + W2T ----------------
__global__ void __launch_bounds__(256)
setup_kernel(const float* __restrict__ W3, const float* __restrict__ b3,
             const float* __restrict__ W_out, const float* __restrict__ b_out,
             const float* __restrict__ props, const float* __restrict__ W_prop,
             const float* __restrict__ b_prop, const float* __restrict__ W_add,
             const float* __restrict__ b_add, const float* __restrict__ b1,
             const float* __restrict__ W_in, const float* __restrict__ W_msg,
             const float* __restrict__ W_upd, const float* __restrict__ W1,
             const float* __restrict__ W2)
{
    int bid = blockIdx.x;
    int tid = threadIdx.x;
    if (bid >= W2T_BLK0) {
        // W2T[n][k] = bf16(W2[k][n]); 64 blocks x 4 n-rows
        int n0 = (bid - W2T_BLK0) * 4;
        #pragma unroll
        for (int j = 0; j < 4; j++)
            g_W2T[(size_t)(n0 + j)*256 + tid] = __float2bfloat16(W2[(size_t)tid*256 + n0 + j]);
    } else if (bid >= 201) {
        int i = ((bid - 201) * 256 + tid) * 4;
        if (i >= WR_TOTAL) return;
        const float* src;
        int off;
        if      (i < OFF_MSG) { src = W_in;  off = OFF_IN;  }
        else if (i < OFF_UPD) { src = W_msg; off = OFF_MSG; }
        else if (i < OFF_ADD) { src = W_upd; off = OFF_UPD; }
        else if (i < OFF_W1)  { src = W_add; off = OFF_ADD; }
        else if (i < OFF_W2)  { src = W1;    off = OFF_W1;  }
        else                  { src = W2;    off = OFF_W2;  }
        float4 v = *(const float4*)&src[i - off];
        v.x = roundtf(v.x); v.y = roundtf(v.y); v.z = roundtf(v.z); v.w = roundtf(v.w);
        *(float4*)&g_Wr[i] = v;
    } else if (bid < 64) {
        __shared__ float pe[64];
        __shared__ float padd[256];
        if (tid < 64) pe[tid] = props[bid] * W_prop[tid] + b_prop[tid];
        __syncthreads();
        {
            float s = b_add[tid];
            #pragma unroll 8
            for (int p = 0; p < 64; p++) s += pe[p] * W_add[(256 + p)*256 + tid];
            padd[tid] = s;
        }
        __syncthreads();
        float a = b1[tid], b = 0.f;
        for (int t = 0; t < 256; t++) {
            float pv = padd[t];
            a += pv * W1[(size_t)t*256 + tid];
            b += pv * W1[(size_t)(256 + t)*256 + tid];
        }
        g_pa[bid*256 + tid] = a;
        g_pb[bid*256 + tid] = b;
    } else if (bid < 72) {
        int t = (bid - 64)*32 + (tid >> 3);
        int l = tid & 7;
        float s[5] = {0.f,0.f,0.f,0.f,0.f};
        for (int j = l; j < 512; j += 8) {
            float w3 = W3[t*512 + j];
            #pragma unroll
            for (int c = 0; c < 5; c++) s[c] += w3 * W_out[j*5 + c];
        }
        #pragma unroll
        for (int off = 4; off; off >>= 1)
            #pragma unroll
            for (int c = 0; c < 5; c++) s[c] += __shfl_down_sync(0xffffffffu, s[c], off, 8);
        if (l == 0) {
            #pragma unroll
            for (int c = 0; c < 5; c++) g_WfoldT[c*256 + t] = s[c];
        }
    } else if (bid == 72) {
        if (tid < 5) {
            float s = b_out[tid];
            for (int k = 0; k < 512; k++) s += b3[k] * W_out[k*5 + tid];
            g_bfold[tid] = s;
        }
        if (tid == 32) g_acc = 0.0;
    } else {
        int q = bid - 73;
        int isB = q >= 64;
        int k0 = (q & 63) * 4;
        const float* W1p = W1 + (isB ? 256*256 : 0);
        float s0 = 0.f, s1 = 0.f, s2 = 0.f, s3 = 0.f;
        for (int t = 0; t < 256; t++) {
            float w = W1p[(size_t)t*256 + tid];
            s0 += W_add[(k0+0)*256 + t] * w;
            s1 += W_add[(k0+1)*256 + t] * w;
            s2 += W_add[(k0+2)*256 + t] * w;
            s3 += W_add[(k0+3)*256 + t] * w;
        }
        float* dstp = g_WAB + (size_t)isB*65536 + (size_t)k0*256;
        dstp[0*256 + tid] = roundtf(s0);
        dstp[1*256 + tid] = roundtf(s1);
        dstp[2*256 + tid] = roundtf(s2);
        dstp[3*256 + tid] = roundtf(s3);
    }
}

// ---------------- edge scatter (R11 config) ----------------
__global__ void __launch_bounds__(256)
edge_scatter(const int* __restrict__ src, const int* __restrict__ dst,
             const float* __restrict__ ea, const float* __restrict__ W_msg,
             const float* __restrict__ b_msg, const float* __restrict__ Hm,
             float* __restrict__ agg, int E)
{
    __shared__ float We[5][256];
    __shared__ float bm[256];
    __shared__ float eas[32][5];
    __shared__ int   ss[32], ds[32];
    int tid = threadIdx.x;
    const float* Wep = W_msg + 256*256;
    for (int i = tid; i < 5*256; i += 256) ((float*)We)[i] = Wep[i];
    bm[tid] = b_msg[tid];
    int e0 = blockIdx.x * 32;
    if (tid < 32 && e0 + tid < E) { ss[tid] = src[e0+tid]; ds[tid] = dst[e0+tid]; }
    if (tid >= 64 && tid < 64 + 160) {
        int i = tid - 64;
        if ((size_t)e0*5 + i < (size_t)E*5) eas[i/5][i%5] = ea[(size_t)e0*5 + i];
    }
    __syncthreads();
    #pragma unroll 4
    for (int q = 0; q < 32; q++) {
        int e = e0 + q;
        if (e >= E) break;
        float v = bm[tid]
                + eas[q][0]*We[0][tid] + eas[q][1]*We[1][tid] + eas[q][2]*We[2][tid]
                + eas[q][3]*We[3][tid] + eas[q][4]*We[4][tid]
                + Hm[(size_t)ss[q]*256 + tid];
        v = fmaxf(v, 0.f);
        atomicAdd(&agg[(size_t)ds[q]*256 + tid], v);
    }
}

// ---------------- tf32 tensor-core SGEMM (R11 verbatim) ----------------
#define APAD 68
#define WPAD 72
template<int CVTA, int CVTA2>
__global__ void __launch_bounds__(256)
sgemm_tc(const float* __restrict__ A1, const float* __restrict__ W1, int K1,
         const float* __restrict__ A2, const float* __restrict__ W2, int K2,
         const float* bias, const float* rowBias,
         float* C, int doRelu, int doRound,
         const float* __restrict__ Wd, float* Cd, int dualSplit,
         float* __restrict__ zeroBuf, const float* rowBiasD)
{
    extern __shared__ float sm[];
    float* Asm = sm;                   // [2][64][APAD]
    float* Wsm = sm + 2*64*APAD;       // [2][64][WPAD]

    int tid = threadIdx.x;
    int wid = tid >> 5;
    int lane = tid & 31;
    int warp_m = wid & 1;
    int warp_n = wid >> 1;
    int gi = lane >> 2;
    int tg = lane & 3;

    int m0 = blockIdx.y * 64;
    int n0;
    const float* PW1 = W1;
    if (dualSplit && (int)blockIdx.x >= dualSplit) {
        PW1 = Wd; C = Cd; bias = nullptr; rowBias = rowBiasD;
        n0 = ((int)blockIdx.x - dualSplit) * 64;
    } else {
        n0 = blockIdx.x * 64;
    }

    float acc[2][2][4];
    #pragma unroll
    for (int mt = 0; mt < 2; mt++)
        #pragma unroll
        for (int nt = 0; nt < 2; nt++)
            #pragma unroll
            for (int q = 0; q < 4; q++) acc[mt][nt][q] = 0.f;

    int lr[4], lc[4];
    #pragma unroll
    for (int i = 0; i < 4; i++) { int f = tid + i*256; lr[i] = f >> 4; lc[i] = (f & 15) * 4; }

    for (int pass = 0; pass < 2; pass++) {
        const float* A = pass ? A2 : A1;
        const float* W = pass ? W2 : PW1;
        int K = pass ? K2 : K1;
        if (K == 0) break;
        int nit = K >> 6;
        int cvtA = pass ? CVTA2 : CVTA;

        #pragma unroll
        for (int i = 0; i < 4; i++) {
            cp_async16(&Asm[0*64*APAD + lr[i]*APAD + lc[i]],
                       &A[(size_t)(m0 + lr[i])*K + lc[i]]);
            cp_async16(&Wsm[0*64*WPAD + lr[i]*WPAD + lc[i]],
                       &W[(size_t)lr[i]*256 + n0 + lc[i]]);
        }
        cp_commit();

        for (int it = 0; it < nit; it++) {
            int cur = it & 1;
            if (it + 1 < nit) {
                int nb = cur ^ 1;
                int k0n = (it + 1) << 6;
                #pragma unroll
                for (int i = 0; i < 4; i++) {
                    cp_async16(&Asm[nb*64*APAD + lr[i]*APAD + lc[i]],
                               &A[(size_t)(m0 + lr[i])*K + k0n + lc[i]]);
                    cp_async16(&Wsm[nb*64*WPAD + lr[i]*WPAD + lc[i]],
                               &W[(size_t)(k0n + lr[i])*256 + n0 + lc[i]]);
                }
                cp_commit();
                cp_wait<1>();
            } else {
                cp_wait<0>();
            }
            __syncthreads();

            const float* Ab = Asm + cur*64*APAD;
            const float* Wb = Wsm + cur*64*WPAD;
            #pragma unroll
            for (int kb = 0; kb < 8; kb++) {
                int k8 = kb*8;
                uint32_t a[2][4];
                #pragma unroll
                for (int mt = 0; mt < 2; mt++) {
                    int m = warp_m*32 + mt*16 + gi;
                    if (cvtA) {
                        a[mt][0] = f2tf32(Ab[(m    )*APAD + k8 + tg    ]);
                        a[mt][1] = f2tf32(Ab[(m + 8)*APAD + k8 + tg    ]);
                        a[mt][2] = f2tf32(Ab[(m    )*APAD + k8 + tg + 4]);
                        a[mt][3] = f2tf32(Ab[(m + 8)*APAD + k8 + tg + 4]);
                    } else {
                        a[mt][0] = __float_as_uint(Ab[(m    )*APAD + k8 + tg    ]);
                        a[mt][1] = __float_as_uint(Ab[(m + 8)*APAD + k8 + tg    ]);
                        a[mt][2] = __float_as_uint(Ab[(m    )*APAD + k8 + tg + 4]);
                        a[mt][3] = __float_as_uint(Ab[(m + 8)*APAD + k8 + tg + 4]);
                    }
                }
                #pragma unroll
                for (int nt = 0; nt < 2; nt++) {
                    int n = warp_n*16 + nt*8 + gi;
                    uint32_t b0 = __float_as_uint(Wb[(k8 + tg    )*WPAD + n]);
                    uint32_t b1 = __float_as_uint(Wb[(k8 + tg + 4)*WPAD + n]);
                    #pragma unroll
                    for (int mt = 0; mt < 2; mt++)
                        mma_tf32(acc[mt][nt][0], acc[mt][nt][1], acc[mt][nt][2], acc[mt][nt][3],
                                 a[mt][0], a[mt][1], a[mt][2], a[mt][3], b0, b1);
                }
            }
            __syncthreads();
        }
    }

    #pragma unroll
    for (int mt = 0; mt < 2; mt++) {
        #pragma unroll
        for (int half = 0; half < 2; half++) {
            int m = m0 + warp_m*32 + mt*16 + gi + half*8;
            #pragma unroll
            for (int nt = 0; nt < 2; nt++) {
                int n = n0 + warp_n*16 + nt*8 + tg*2;
                float v0 = acc[mt][nt][half*2 + 0];
                float v1 = acc[mt][nt][half*2 + 1];
                if (bias)    { v0 += bias[n]; v1 += bias[n+1]; }
                if (rowBias) {
                    const float* rb = rowBias + ((m >> 6) << 8);
                    v0 += rb[n]; v1 += rb[n+1];
                }
                if (doRelu)  { v0 = fmaxf(v0, 0.f); v1 = fmaxf(v1, 0.f); }
                if (doRound) { v0 = roundtf(v0); v1 = roundtf(v1); }
                *(float2*)&C[(size_t)m*256 + n] = make_float2(v0, v1);
                if (zeroBuf) *(float2*)&zeroBuf[(size_t)m*256 + n] = make_float2(0.f, 0.f);
            }
        }
    }
}

// ---------------- pair megakernel: bf16 MMA (m16n8k16), 128 rows/block ----------------
// h1 bf16 in smem [128][132 u32-pairs]; W2T chunks [256n][20 u32] double-buffered.
#define H1W 132
#define WCH 20
__global__ void __launch_bounds__(512, 1)
pair_kernel(const float* __restrict__ Ag, const float* __restrict__ Bg,
            const int* __restrict__ sel_b, const int* __restrict__ sel_i,
            const int* __restrict__ sel_j, const int* __restrict__ golden,
            const __nv_bfloat16* __restrict__ W2T, const float* __restrict__ b2)
{
    extern __shared__ uint32_t smem[];
    uint32_t* h1u = smem;                      // [128][H1W] bf16x2; reused for h2 bf16x2
    uint32_t* w2u = h1u + 128*H1W;             // [2][256*WCH]
    float*    wfs = (float*)(w2u + 2*256*WCH); // [5][256]
    float*    b2s = wfs + 5*256;               // [256]
    float*    bfs = b2s + 256;                 // [8]

    int tid  = threadIdx.x;
    int wid  = tid >> 5;
    int lane = tid & 31;
    int warp_m = wid & 3;
    int warp_n = wid >> 2;
    int gi = lane >> 2;
    int tg = lane & 3;
    int e0 = blockIdx.x * 128;

    const char* W2Tb = (const char*)W2T;   // row stride 512 B

    // W2T chunk fill: 1024 cp16 per chunk, 2 per thread
    int t_row[2], t_seg[2];
    #pragma unroll
    for (int i = 0; i < 2; i++) { int f = tid + i*512; t_row[i] = f >> 2; t_seg[i] = f & 3; }

    // prefetch chunk 0 under gather
    #pragma unroll
    for (int i = 0; i < 2; i++)
        cp_async16(&w2u[0*256*WCH + t_row[i]*WCH + t_seg[i]*4],
                   W2Tb + (size_t)t_row[i]*512 + t_seg[i]*16);
    cp_commit();

    for (int i = tid; i < 5*256; i += 512) wfs[i] = g_WfoldT[i];
    if (tid < 256) b2s[tid] = b2[tid];
    if (tid < 5) bfs[tid] = g_bfold[tid];

    // gather: h1 = relu(A[bi*64+si] + B[bi*64+sj]), stored bf16x2
    #pragma unroll
    for (int t = 0; t < 8; t++) {
        int r = wid*8 + t;
        int e = e0 + r;
        int bsel = sel_b[e];
        int ii = bsel*64 + sel_i[e];
        int jj = bsel*64 + sel_j[e];
        const float* ap = Ag + (size_t)ii*256;
        const float* bp = Bg + (size_t)jj*256;
        #pragma unroll
        for (int q = 0; q < 2; q++) {
            int c = lane*4 + q*128;
            float4 av = *(const float4*)(ap + c);
            float4 bv = *(const float4*)(bp + c);
            int col = (c >> 1);
            h1u[r*H1W + col    ] = f2bf2(fmaxf(av.x + bv.x, 0.f), fmaxf(av.y + bv.y, 0.f));
            h1u[r*H1W + col + 1] = f2bf2(fmaxf(av.z + bv.z, 0.f), fmaxf(av.w + bv.w, 0.f));
        }
    }

    float acc[2][8][4];
    #pragma unroll
    for (int mt = 0; mt < 2; mt++)
        #pragma unroll
        for (int nt = 0; nt < 8; nt++)
            #pragma unroll
            for (int q = 0; q < 4; q++) acc[mt][nt][q] = 0.f;

    for (int kc = 0; kc < 8; kc++) {
        int cur = kc & 1;
        if (kc + 1 < 8) {
            int nb = cur ^ 1;
            #pragma unroll
            for (int i = 0; i < 2; i++)
                cp_async16(&w2u[nb*256*WCH + t_row[i]*WCH + t_seg[i]*4],
                           W2Tb + (size_t)t_row[i]*512 + (kc + 1)*64 + t_seg[i]*16);
            cp_commit();
            cp_wait<1>();
        } else {
            cp_wait<0>();
        }
        __syncthreads();

        const uint32_t* wb = w2u + cur*256*WCH;
        #pragma unroll
        for (int ks = 0; ks < 2; ks++) {
            int kb = kc*16 + ks*8;     // u32 column base in h1
            uint32_t a[2][4];
            #pragma unroll
            for (int mt = 0; mt < 2; mt++) {
                int m = warp_m*32 + mt*16 + gi;
                a[mt][0] = h1u[(m    )*H1W + kb + tg    ];
                a[mt][1] = h1u[(m + 8)*H1W + kb + tg    ];
                a[mt][2] = h1u[(m    )*H1W + kb + tg + 4];
                a[mt][3] = h1u[(m + 8)*H1W + kb + tg + 4];
            }
            #pragma unroll
            for (int nt = 0; nt < 8; nt++) {
                int n = warp_n*64 + nt*8 + gi;
                uint32_t b0 = wb[n*WCH + ks*8 + tg    ];
                uint32_t b1 = wb[n*WCH + ks*8 + tg + 4];
                #pragma unroll
                for (int mt = 0; mt < 2; mt++)
                    mma_bf16(acc[mt][nt][0], acc[mt][nt][1], acc[mt][nt][2], acc[mt][nt][3],
                             a[mt][0], a[mt][1], a[mt][2], a[mt][3], b0, b1);
            }
        }
        __syncthreads();
    }

    // h2 = relu(acc + b2), re-stored as bf16x2 over h1
    #pragma unroll
    for (int mt = 0; mt < 2; mt++) {
        #pragma unroll
        for (int half = 0; half < 2; half++) {
            int m = warp_m*32 + mt*16 + gi + half*8;
            #pragma unroll
            for (int nt = 0; nt < 8; nt++) {
                int n = warp_n*64 + nt*8 + tg*2;
                float v0 = fmaxf(acc[mt][nt][half*2 + 0] + b2s[n],     0.f);
                float v1 = fmaxf(acc[mt][nt][half*2 + 1] + b2s[n + 1], 0.f);
                h1u[m*H1W + (n >> 1)] = f2bf2(v0, v1);
            }
        }
    }
    __syncthreads();

    // logits + loss
    double lsum = 0.0;
    for (int t = 0; t < 8; t++) {
        int r = wid*8 + t;
        float p[5] = {0.f,0.f,0.f,0.f,0.f};
        #pragma unroll
        for (int m4 = 0; m4 < 4; m4++) {
            int ku = lane + 32*m4;             // u32 index 0..127
            uint32_t u = h1u[r*H1W + ku];
            float2 hv = __bfloat1622float2(*reinterpret_cast<__nv_bfloat162*>(&u));
            int k = ku*2;
            #pragma unroll
            for (int c = 0; c < 5; c++)
                p[c] += hv.x * wfs[c*256 + k] + hv.y * wfs[c*256 + k + 1];
        }
        #pragma unroll
        for (int off = 16; off; off >>= 1)
            #pragma unroll
            for (int c = 0; c < 5; c++) p[c] += __shfl_xor_sync(0xffffffffu, p[c], off);
        if (lane == 0) {
            float lg[5], mx = -1e30f;
            #pragma unroll
            for (int c = 0; c < 5; c++) { lg[c] = p[c] + bfs[c]; mx = fmaxf(mx, lg[c]); }
            float s = 0.f;
            #pragma unroll
            for (int c = 0; c < 5; c++) s += expf(lg[c] - mx);
            float lse = mx + logf(s);
            int gold = golden[e0 + r];
            lsum += (double)(lse - lg[gold]);
        }
    }
    if (lane == 0) atomicAdd(&g_acc, lsum);
}

// ---------------- finalize ----------------
__global__ void finalize_kernel(float* __restrict__ out, int esel)
{
    out[0] = (float)(g_acc / (double)esel);
}

// ---------------- host launcher ----------------
extern "C" void kernel_launch(void* const* d_in, const int* in_sizes, int n_in,
                              void* d_out, int out_size)
{
    const float* x         = (const float*)d_in[0];
    const int*   eidx      = (const int*)  d_in[1];
    const float* edge_attr = (const float*)d_in[2];
    const float* props     = (const float*)d_in[3];
    const int*   sel_b     = (const int*)  d_in[4];
    const int*   sel_i     = (const int*)  d_in[5];
    const int*   sel_j     = (const int*)  d_in[6];
    const int*   golden    = (const int*)  d_in[7];
    const float* W_prop = (const float*)d_in[8];
    const float* b_prop = (const float*)d_in[9];
    const float* W_in   = (const float*)d_in[10];
    const float* b_in   = (const float*)d_in[11];
    const float* W_msg  = (const float*)d_in[12];
    const float* b_msg  = (const float*)d_in[13];
    const float* W_upd  = (const float*)d_in[14];
    const float* b_upd  = (const float*)d_in[15];
    const float* W_add  = (const float*)d_in[16];
    const float* b_add  = (const float*)d_in[17];
    const float* W1     = (const float*)d_in[18];
    const float* b1     = (const float*)d_in[19];
    const float* W2     = (const float*)d_in[20];
    const float* b2     = (const float*)d_in[21];
    const float* W3     = (const float*)d_in[22];
    const float* b3     = (const float*)d_in[23];
    const float* W_out  = (const float*)d_in[24];
    const float* b_out  = (const float*)d_in[25];

    int E    = in_sizes[1] / 2;
    int ESEL = in_sizes[4];
    const int* src = eidx;
    const int* dst = eidx + E;

    float *p_h, *p_ht, *p_agg, *p_A, *p_B, *p_Hm, *p_Wr, *p_WAB, *p_pa, *p_pb;
    __nv_bfloat16* p_W2T;
    cudaGetSymbolAddress((void**)&p_h,    g_h);
    cudaGetSymbolAddress((void**)&p_ht,   g_ht);
    cudaGetSymbolAddress((void**)&p_agg,  g_agg);
    cudaGetSymbolAddress((void**)&p_A,    g_A);
    cudaGetSymbolAddress((void**)&p_B,    g_B);
    cudaGetSymbolAddress((void**)&p_Hm,   g_Hm);
    cudaGetSymbolAddress((void**)&p_Wr,   g_Wr);
    cudaGetSymbolAddress((void**)&p_WAB,  g_WAB);
    cudaGetSymbolAddress((void**)&p_pa,   g_pa);
    cudaGetSymbolAddress((void**)&p_pb,   g_pb);
    cudaGetSymbolAddress((void**)&p_W2T,  g_W2T);

    int gemmSmem = (2*64*APAD + 2*64*WPAD) * (int)sizeof(float);
    cudaFuncSetAttribute((const void*)sgemm_tc<0,0>, cudaFuncAttributeMaxDynamicSharedMemorySize, gemmSmem);
    cudaFuncSetAttribute((const void*)sgemm_tc<1,0>, cudaFuncAttributeMaxDynamicSharedMemorySize, gemmSmem);
    cudaFuncSetAttribute((const void*)sgemm_tc<0,1>, cudaFuncAttributeMaxDynamicSharedMemorySize, gemmSmem);
    int pairSmem = (128*H1W + 2*256*WCH + 5*256 + 256 + 8) * (int)sizeof(uint32_t);  // ~112 KB
    cudaFuncSetAttribute(pair_kernel, cudaFuncAttributeMaxDynamicSharedMemorySize, pairSmem);

    dim3 gemmGrid(4, BNODES/64);
    dim3 gemmGridDual(8, BNODES/64);

    const float* Wr_in  = p_Wr + OFF_IN;
    const float* Wr_msg = p_Wr + OFF_MSG;
    const float* Wr_upd = p_Wr + OFF_UPD;
    const float* WA_r   = p_WAB;
    const float* WB_r   = p_WAB + 65536;

    // ---- one-time setup ----
    setup_kernel<<<W2T_BLK0 + 64, 256>>>(W3, b3, W_out, b_out, props, W_prop, b_prop,
                                         W_add, b_add, b1, W_in, W_msg, W_upd, W1, W2);

    // h0 = relu(x @ W_in + b_in), rounded (x unrounded -> CVTA=1)
    sgemm_tc<1,0><<<gemmGrid, 256, gemmSmem>>>(x, Wr_in, 192, nullptr, nullptr, 0,
                                               b_in, nullptr, p_h, 1, 1,
                                               nullptr, nullptr, 0, nullptr, nullptr);

    float* cur = p_h;
    float* nxt = p_ht;
    for (int t = 0; t < 4; t++) {
        // Hm = round(h @ W_msg); epilogue also zeroes agg
        sgemm_tc<0,0><<<gemmGrid, 256, gemmSmem>>>(cur, Wr_msg, 256, nullptr, nullptr, 0,
                                                   nullptr, nullptr, p_Hm, 0, 1,
                                                   nullptr, nullptr, 0, p_agg, nullptr);
        // agg[dst] += relu(Hm[src] + b_msg + ea@We)
        edge_scatter<<<(E + 31)/32, 256>>>(src, dst, edge_attr, W_msg, b_msg, p_Hm, p_agg, E);
        // h' = relu(h@W_upd_top + agg@W_upd_bot + b_upd), agg cvt at read
        sgemm_tc<0,1><<<gemmGrid, 256, gemmSmem>>>(cur, Wr_upd, 256, p_agg, Wr_upd + 256*256, 256,
                                                   b_upd, nullptr, nxt, 1, 1,
                                                   nullptr, nullptr, 0, nullptr, nullptr);
        float* tmp = cur; cur = nxt; nxt = tmp;
    }

    // A = h@WA + pa[batch] ; B = h@WB + pb[batch]  (one dual launch)
    sgemm_tc<0,0><<<gemmGridDual, 256, gemmSmem>>>(cur, WA_r, 256, nullptr, nullptr, 0,
                                                   nullptr, p_pa, p_A, 0, 0,
                                                   WB_r, p_B, 4, nullptr, p_pb);

    // pair stage + loss (bf16 MMA)
    pair_kernel<<<ESEL/128, 512, pairSmem>>>(p_A, p_B, sel_b, sel_i, sel_j, golden, p_W2T, b2);

    finalize_kernel<<<1, 1>>>((float*)d_out, ESEL);
}

// round 14
// speedup vs baseline: 1.2214x; 1.0290x over previous
#include <cuda_runtime.h>
#include <cuda_bf16.h>
#include <math.h>
#include <stdint.h>

// ---------------- problem constants ----------------
#define BNODES   4096      // B*N
#define HDIM     256
#define EMAX     16384

// rounded-weight buffer offsets (floats)
#define OFF_IN   0                    // 192*256
#define OFF_MSG  49152                // 256*256
#define OFF_UPD  114688               // 512*256
#define OFF_ADD  245760               // (spacer)
#define OFF_W1   311296               // (spacer)
#define OFF_W2   442368               // 256*256
#define WR_TOTAL 507904
#define RW_BLOCKS ((WR_TOTAL/4 + 255)/256)   // 496
#define W2T_BLK0 (201 + RW_BLOCKS)           // 697

// ---------------- scratch (device globals, no allocs) ----------------
__device__ float g_h   [BNODES*HDIM];
__device__ float g_ht  [BNODES*HDIM];
__device__ float g_Hm  [BNODES*HDIM];
__device__ float g_P   [BNODES*HDIM];
__device__ float g_agg [BNODES*HDIM];
__device__ float g_A   [BNODES*HDIM];
__device__ float g_B   [BNODES*HDIM];
__device__ float g_Wr  [WR_TOTAL];
__device__ float g_WAB [2*HDIM*HDIM];  // WA, WB (tf32-rounded)
__device__ float g_pa  [64*HDIM];
__device__ float g_pb  [64*HDIM];
__device__ __nv_bfloat16 g_W2T[HDIM*HDIM];  // W2 transposed [n][k], bf16
__device__ float g_WfoldT[5*HDIM];
__device__ float g_bfold[8];
__device__ double g_acc;

// ---------------- helpers ----------------
__device__ __forceinline__ uint32_t f2tf32(float x) {
    uint32_t r;
    asm("cvt.rna.tf32.f32 %0, %1;" : "=r"(r) : "f"(x));
    return r;
}
__device__ __forceinline__ float roundtf(float x) { return __uint_as_float(f2tf32(x)); }

__device__ __forceinline__ uint32_t f2bf2(float lo, float hi) {
    uint32_t r;
    asm("cvt.rn.bf16x2.f32 %0, %1, %2;" : "=r"(r) : "f"(hi), "f"(lo));
    return r;
}

__device__ __forceinline__ void mma_tf32(float& d0, float& d1, float& d2, float& d3,
                                         uint32_t a0, uint32_t a1, uint32_t a2, uint32_t a3,
                                         uint32_t b0, uint32_t b1)
{
    asm volatile(
        "mma.sync.aligned.m16n8k8.row.col.f32.tf32.tf32.f32 "
        "{%0,%1,%2,%3}, {%4,%5,%6,%7}, {%8,%9}, {%0,%1,%2,%3};"
        : "+f"(d0), "+f"(d1), "+f"(d2), "+f"(d3)
        : "r"(a0), "r"(a1), "r"(a2), "r"(a3), "r"(b0), "r"(b1));
}

__device__ __forceinline__ void mma_bf16(float& d0, float& d1, float& d2, float& d3,
                                         uint32_t a0, uint32_t a1, uint32_t a2, uint32_t a3,
                                         uint32_t b0, uint32_t b1)
{
    asm volatile(
        "mma.sync.aligned.m16n8k16.row.col.f32.bf16.bf16.f32 "
        "{%0,%1,%2,%3}, {%4,%5,%6,%7}, {%8,%9}, {%0,%1,%2,%3};"
        : "+f"(d0), "+f"(d1), "+f"(d2), "+f"(d3)
        : "r"(a0), "r"(a1), "r"(a2), "r"(a3), "r"(b0), "r"(b1));
}

__device__ __forceinline__ void cp_async16(void* smem_ptr, const void* gmem_ptr)
{
    uint32_t s = (uint32_t)__cvta_generic_to_shared(smem_ptr);
    asm volatile("cp.async.cg.shared.global [%0], [%1], 16;" :: "r"(s), "l"(gmem_ptr));
}
__device__ __forceinline__ void cp_commit() { asm volatile("cp.async.commit_group;"); }
template<int N> __device__ __forceinline__ void cp_wait() {
    asm volatile("cp.async.wait_group %0;" :: "n"(N));
}

// ---------------- setup: folds + pa/pb + WA/WB + weight rounding + W2T ----------------
__global__ void __launch_bounds__(256)
setup_kernel(const float* __restrict__ W3, const float* __restrict__ b3,
             const float* __restrict__ W_out, const float* __restrict__ b_out,
             const float* __restrict__ props, const float* __restrict__ W_prop,
             const float* __restrict__ b_prop, const float* __restrict__ W_add,
             const float* __restrict__ b_add, const float* __restrict__ b1,
             const float* __restrict__ W_in, const float* __restrict__ W_msg,
             const float* __restrict__ W_upd, const float* __restrict__ W1,
             const float* __restrict__ W2)
{
    int bid = blockIdx.x;
    int tid = threadIdx.x;
    if (bid >= W2T_BLK0) {
        int n0 = (bid - W2T_BLK0) * 4;
        #pragma unroll
        for (int j = 0; j < 4; j++)
            g_W2T[(size_t)(n0 + j)*256 + tid] = __float2bfloat16(W2[(size_t)tid*256 + n0 + j]);
    } else if (bid >= 201) {
        int i = ((bid - 201) * 256 + tid) * 4;
        if (i >= WR_TOTAL) return;
        const float* src;
        int off;
        if      (i < OFF_MSG) { src = W_in;  off = OFF_IN;  }
        else if (i < OFF_UPD) { src = W_msg; off = OFF_MSG; }
        else if (i < OFF_ADD) { src = W_upd; off = OFF_UPD; }
        else if (i < OFF_W1)  { src = W_add; off = OFF_ADD; }
        else if (i < OFF_W2)  { src = W1;    off = OFF_W1;  }
        else                  { src = W2;    off = OFF_W2;  }
        float4 v = *(const float4*)&src[i - off];
        v.x = roundtf(v.x); v.y = roundtf(v.y); v.z = roundtf(v.z); v.w = roundtf(v.w);
        *(float4*)&g_Wr[i] = v;
    } else if (bid < 64) {
        __shared__ float pe[64];
        __shared__ float padd[256];
        if (tid < 64) pe[tid] = props[bid] * W_prop[tid] + b_prop[tid];
        __syncthreads();
        {
            float s = b_add[tid];
            #pragma unroll 8
            for (int p = 0; p < 64; p++) s += pe[p] * W_add[(256 + p)*256 + tid];
            padd[tid] = s;
        }
        __syncthreads();
        float a = b1[tid], b = 0.f;
        for (int t = 0; t < 256; t++) {
            float pv = padd[t];
            a += pv * W1[(size_t)t*256 + tid];
            b += pv * W1[(size_t)(256 + t)*256 + tid];
        }
        g_pa[bid*256 + tid] = a;
        g_pb[bid*256 + tid] = b;
    } else if (bid < 72) {
        int t = (bid - 64)*32 + (tid >> 3);
        int l = tid & 7;
        float s[5] = {0.f,0.f,0.f,0.f,0.f};
        for (int j = l; j < 512; j += 8) {
            float w3 = W3[t*512 + j];
            #pragma unroll
            for (int c = 0; c < 5; c++) s[c] += w3 * W_out[j*5 + c];
        }
        #pragma unroll
        for (int off = 4; off; off >>= 1)
            #pragma unroll
            for (int c = 0; c < 5; c++) s[c] += __shfl_down_sync(0xffffffffu, s[c], off, 8);
        if (l == 0) {
            #pragma unroll
            for (int c = 0; c < 5; c++) g_WfoldT[c*256 + t] = s[c];
        }
    } else if (bid == 72) {
        if (tid < 5) {
            float s = b_out[tid];
            for (int k = 0; k < 512; k++) s += b3[k] * W_out[k*5 + tid];
            g_bfold[tid] = s;
        }
        if (tid == 32) g_acc = 0.0;
    } else {
        int q = bid - 73;
        int isB = q >= 64;
        int k0 = (q & 63) * 4;
        const float* W1p = W1 + (isB ? 256*256 : 0);
        float s0 = 0.f, s1 = 0.f, s2 = 0.f, s3 = 0.f;
        for (int t = 0; t < 256; t++) {
            float w = W1p[(size_t)t*256 + tid];
            s0 += W_add[(k0+0)*256 + t] * w;
            s1 += W_add[(k0+1)*256 + t] * w;
            s2 += W_add[(k0+2)*256 + t] * w;
            s3 += W_add[(k0+3)*256 + t] * w;
        }
        float* dstp = g_WAB + (size_t)isB*65536 + (size_t)k0*256;
        dstp[0*256 + tid] = roundtf(s0);
        dstp[1*256 + tid] = roundtf(s1);
        dstp[2*256 + tid] = roundtf(s2);
        dstp[3*256 + tid] = roundtf(s3);
    }
}

// ---------------- edge scatter (R11 config) ----------------
__global__ void __launch_bounds__(256)
edge_scatter(const int* __restrict__ src, const int* __restrict__ dst,
             const float* __restrict__ ea, const float* __restrict__ W_msg,
             const float* __restrict__ b_msg, const float* __restrict__ Hm,
             float* __restrict__ agg, int E)
{
    __shared__ float We[5][256];
    __shared__ float bm[256];
    __shared__ float eas[32][5];
    __shared__ int   ss[32], ds[32];
    int tid = threadIdx.x;
    const float* Wep = W_msg + 256*256;
    for (int i = tid; i < 5*256; i += 256) ((float*)We)[i] = Wep[i];
    bm[tid] = b_msg[tid];
    int e0 = blockIdx.x * 32;
    if (tid < 32 && e0 + tid < E) { ss[tid] = src[e0+tid]; ds[tid] = dst[e0+tid]; }
    if (tid >= 64 && tid < 64 + 160) {
        int i = tid - 64;
        if ((size_t)e0*5 + i < (size_t)E*5) eas[i/5][i%5] = ea[(size_t)e0*5 + i];
    }
    __syncthreads();
    #pragma unroll 4
    for (int q = 0; q < 32; q++) {
        int e = e0 + q;
        if (e >= E) break;
        float v = bm[tid]
                + eas[q][0]*We[0][tid] + eas[q][1]*We[1][tid] + eas[q][2]*We[2][tid]
                + eas[q][3]*We[3][tid] + eas[q][4]*We[4][tid]
                + Hm[(size_t)ss[q]*256 + tid];
        v = fmaxf(v, 0.f);
        atomicAdd(&agg[(size_t)ds[q]*256 + tid], v);
    }
}

// ---------------- tf32 tensor-core SGEMM (R11 core + addBuf) ----------------
#define APAD 68
#define WPAD 72
template<int CVTA>
__global__ void __launch_bounds__(256)
sgemm_tc(const float* __restrict__ A1, const float* __restrict__ W1, int K1,
         const float* bias, const float* rowBias,
         float* C, int doRelu, int doRound,
         float* __restrict__ zeroBuf, const float* __restrict__ addBuf)
{
    extern __shared__ float sm[];
    float* Asm = sm;                   // [2][64][APAD]
    float* Wsm = sm + 2*64*APAD;       // [2][64][WPAD]

    int tid = threadIdx.x;
    int wid = tid >> 5;
    int lane = tid & 31;
    int warp_m = wid & 1;
    int warp_n = wid >> 1;
    int gi = lane >> 2;
    int tg = lane & 3;

    int m0 = blockIdx.y * 64;
    int n0 = blockIdx.x * 64;

    float acc[2][2][4];
    #pragma unroll
    for (int mt = 0; mt < 2; mt++)
        #pragma unroll
        for (int nt = 0; nt < 2; nt++)
            #pragma unroll
            for (int q = 0; q < 4; q++) acc[mt][nt][q] = 0.f;

    int lr[4], lc[4];
    #pragma unroll
    for (int i = 0; i < 4; i++) { int f = tid + i*256; lr[i] = f >> 4; lc[i] = (f & 15) * 4; }

    const float* A = A1;
    const float* W = W1;
    int K = K1;
    int nit = K >> 6;

    #pragma unroll
    for (int i = 0; i < 4; i++) {
        cp_async16(&Asm[0*64*APAD + lr[i]*APAD + lc[i]],
                   &A[(size_t)(m0 + lr[i])*K + lc[i]]);
        cp_async16(&Wsm[0*64*WPAD + lr[i]*WPAD + lc[i]],
                   &W[(size_t)lr[i]*256 + n0 + lc[i]]);
    }
    cp_commit();

    for (int it = 0; it < nit; it++) {
        int cur = it & 1;
        if (it + 1 < nit) {
            int nb = cur ^ 1;
            int k0n = (it + 1) << 6;
            #pragma unroll
            for (int i = 0; i < 4; i++) {
                cp_async16(&Asm[nb*64*APAD + lr[i]*APAD + lc[i]],
                           &A[(size_t)(m0 + lr[i])*K + k0n + lc[i]]);
                cp_async16(&Wsm[nb*64*WPAD + lr[i]*WPAD + lc[i]],
                           &W[(size_t)(k0n + lr[i])*256 + n0 + lc[i]]);
            }
            cp_commit();
            cp_wait<1>();
        } else {
            cp_wait<0>();
        }
        __syncthreads();

        const float* Ab = Asm + cur*64*APAD;
        const float* Wb = Wsm + cur*64*WPAD;
        #pragma unroll
        for (int kb = 0; kb < 8; kb++) {
            int k8 = kb*8;
            uint32_t a[2][4];
            #pragma unroll
            for (int mt = 0; mt < 2; mt++) {
                int m = warp_m*32 + mt*16 + gi;
                if (CVTA) {
                    a[mt][0] = f2tf32(Ab[(m    )*APAD + k8 + tg    ]);
                    a[mt][1] = f2tf32(Ab[(m + 8)*APAD + k8 + tg    ]);
                    a[mt][2] = f2tf32(Ab[(m    )*APAD + k8 + tg + 4]);
                    a[mt][3] = f2tf32(Ab[(m + 8)*APAD + k8 + tg + 4]);
                } else {
                    a[mt][0] = __float_as_uint(Ab[(m    )*APAD + k8 + tg    ]);
                    a[mt][1] = __float_as_uint(Ab[(m + 8)*APAD + k8 + tg    ]);
                    a[mt][2] = __float_as_uint(Ab[(m    )*APAD + k8 + tg + 4]);
                    a[mt][3] = __float_as_uint(Ab[(m + 8)*APAD + k8 + tg + 4]);
                }
            }
            #pragma unroll
            for (int nt = 0; nt < 2; nt++) {
                int n = warp_n*16 + nt*8 + gi;
                uint32_t b0 = __float_as_uint(Wb[(k8 + tg    )*WPAD + n]);
                uint32_t b1 = __float_as_uint(Wb[(k8 + tg + 4)*WPAD + n]);
                #pragma unroll
                for (int mt = 0; mt < 2; mt++)
                    mma_tf32(acc[mt][nt][0], acc[mt][nt][1], acc[mt][nt][2], acc[mt][nt][3],
                             a[mt][0], a[mt][1], a[mt][2], a[mt][3], b0, b1);
            }
        }
        __syncthreads();
    }

    #pragma unroll
    for (int mt = 0; mt < 2; mt++) {
        #pragma unroll
        for (int half = 0; half < 2; half++) {
            int m = m0 + warp_m*32 + mt*16 + gi + half*8;
            #pragma unroll
            for (int nt = 0; nt < 2; nt++) {
                int n = n0 + warp_n*16 + nt*8 + tg*2;
                float v0 = acc[mt][nt][half*2 + 0];
                float v1 = acc[mt][nt][half*2 + 1];
                if (bias)    { v0 += bias[n]; v1 += bias[n+1]; }
                if (rowBias) {
                    const float* rb = rowBias + ((m >> 6) << 8);
                    v0 += rb[n]; v1 += rb[n+1];
                }
                if (addBuf) {
                    float2 ad = *(const float2*)&addBuf[(size_t)m*256 + n];
                    v0 += ad.x; v1 += ad.y;
                }
                if (doRelu)  { v0 = fmaxf(v0, 0.f); v1 = fmaxf(v1, 0.f); }
                if (doRound) { v0 = roundtf(v0); v1 = roundtf(v1); }
                *(float2*)&C[(size_t)m*256 + n] = make_float2(v0, v1);
                if (zeroBuf) *(float2*)&zeroBuf[(size_t)m*256 + n] = make_float2(0.f, 0.f);
            }
        }
    }
}

// ---------------- pair megakernel: bf16 MMA (R13 verbatim) ----------------
#define H1W 132
#define WCH 20
__global__ void __launch_bounds__(512, 1)
pair_kernel(const float* __restrict__ Ag, const float* __restrict__ Bg,
            const int* __restrict__ sel_b, const int* __restrict__ sel_i,
            const int* __restrict__ sel_j, const int* __restrict__ golden,
            const __nv_bfloat16* __restrict__ W2T, const float* __restrict__ b2)
{
    extern __shared__ uint32_t smem[];
    uint32_t* h1u = smem;
    uint32_t* w2u = h1u + 128*H1W;
    float*    wfs = (float*)(w2u + 2*256*WCH);
    float*    b2s = wfs + 5*256;
    float*    bfs = b2s + 256;

    int tid  = threadIdx.x;
    int wid  = tid >> 5;
    int lane = tid & 31;
    int warp_m = wid & 3;
    int warp_n = wid >> 2;
    int gi = lane >> 2;
    int tg = lane & 3;
    int e0 = blockIdx.x * 128;

    const char* W2Tb = (const char*)W2T;

    int t_row[2], t_seg[2];
    #pragma unroll
    for (int i = 0; i < 2; i++) { int f = tid + i*512; t_row[i] = f >> 2; t_seg[i] = f & 3; }

    #pragma unroll
    for (int i = 0; i < 2; i++)
        cp_async16(&w2u[0*256*WCH + t_row[i]*WCH + t_seg[i]*4],
                   W2Tb + (size_t)t_row[i]*512 + t_seg[i]*16);
    cp_commit();

    for (int i = tid; i < 5*256; i += 512) wfs[i] = g_WfoldT[i];
    if (tid < 256) b2s[tid] = b2[tid];
    if (tid < 5) bfs[tid] = g_bfold[tid];

    #pragma unroll
    for (int t = 0; t < 8; t++) {
        int r = wid*8 + t;
        int e = e0 + r;
        int bsel = sel_b[e];
        int ii = bsel*64 + sel_i[e];
        int jj = bsel*64 + sel_j[e];
        const float* ap = Ag + (size_t)ii*256;
        const float* bp = Bg + (size_t)jj*256;
        #pragma unroll
        for (int q = 0; q < 2; q++) {
            int c = lane*4 + q*128;
            float4 av = *(const float4*)(ap + c);
            float4 bv = *(const float4*)(bp + c);
            int col = (c >> 1);
            h1u[r*H1W + col    ] = f2bf2(fmaxf(av.x + bv.x, 0.f), fmaxf(av.y + bv.y, 0.f));
            h1u[r*H1W + col + 1] = f2bf2(fmaxf(av.z + bv.z, 0.f), fmaxf(av.w + bv.w, 0.f));
        }
    }

    float acc[2][8][4];
    #pragma unroll
    for (int mt = 0; mt < 2; mt++)
        #pragma unroll
        for (int nt = 0; nt < 8; nt++)
            #pragma unroll
            for (int q = 0; q < 4; q++) acc[mt][nt][q] = 0.f;

    for (int kc = 0; kc < 8; kc++) {
        int cur = kc & 1;
        if (kc + 1 < 8) {
            int nb = cur ^ 1;
            #pragma unroll
            for (int i = 0; i < 2; i++)
                cp_async16(&w2u[nb*256*WCH + t_row[i]*WCH + t_seg[i]*4],
                           W2Tb + (size_t)t_row[i]*512 + (kc + 1)*64 + t_seg[i]*16);
            cp_commit();
            cp_wait<1>();
        } else {
            cp_wait<0>();
        }
        __syncthreads();

        const uint32_t* wb = w2u + cur*256*WCH;
        #pragma unroll
        for (int ks = 0; ks < 2; ks++) {
            int kb = kc*16 + ks*8;
            uint32_t a[2][4];
            #pragma unroll
            for (int mt = 0; mt < 2; mt++) {
                int m = warp_m*32 + mt*16 + gi;
                a[mt][0] = h1u[(m    )*H1W + kb + tg    ];
                a[mt][1] = h1u[(m + 8)*H1W + kb + tg    ];
                a[mt][2] = h1u[(m    )*H1W + kb + tg + 4];
                a[mt][3] = h1u[(m + 8)*H1W + kb + tg + 4];
            }
            #pragma unroll
            for (int nt = 0; nt < 8; nt++) {
                int n = warp_n*64 + nt*8 + gi;
                uint32_t b0 = wb[n*WCH + ks*8 + tg    ];
                uint32_t b1 = wb[n*WCH + ks*8 + tg + 4];
                #pragma unroll
                for (int mt = 0; mt < 2; mt++)
                    mma_bf16(acc[mt][nt][0], acc[mt][nt][1], acc[mt][nt][2], acc[mt][nt][3],
                             a[mt][0], a[mt][1], a[mt][2], a[mt][3], b0, b1);
            }
        }
        __syncthreads();
    }

    #pragma unroll
    for (int mt = 0; mt < 2; mt++) {
        #pragma unroll
        for (int half = 0; half < 2; half++) {
            int m = warp_m*32 + mt*16 + gi + half*8;
            #pragma unroll
            for (int nt = 0; nt < 8; nt++) {
                int n = warp_n*64 + nt*8 + tg*2;
                float v0 = fmaxf(acc[mt][nt][half*2 + 0] + b2s[n],     0.f);
                float v1 = fmaxf(acc[mt][nt][half*2 + 1] + b2s[n + 1], 0.f);
                h1u[m*H1W + (n >> 1)] = f2bf2(v0, v1);
            }
        }
    }
    __syncthreads();

    double lsum = 0.0;
    for (int t = 0; t < 8; t++) {
        int r = wid*8 + t;
        float p[5] = {0.f,0.f,0.f,0.f,0.f};
        #pragma unroll
        for (int m4 = 0; m4 < 4; m4++) {
            int ku = lane + 32*m4;
            uint32_t u = h1u[r*H1W + ku];
            float2 hv = __bfloat1622float2(*reinterpret_cast<__nv_bfloat162*>(&u));
            int k = ku*2;
            #pragma unroll
            for (int c = 0; c < 5; c++)
                p[c] += hv.x * wfs[c*256 + k] + hv.y * wfs[c*256 + k + 1];
        }
        #pragma unroll
        for (int off = 16; off; off >>= 1)
            #pragma unroll
            for (int c = 0; c < 5; c++) p[c] += __shfl_xor_sync(0xffffffffu, p[c], off);
        if (lane == 0) {
            float lg[5], mx = -1e30f;
            #pragma unroll
            for (int c = 0; c < 5; c++) { lg[c] = p[c] + bfs[c]; mx = fmaxf(mx, lg[c]); }
            float s = 0.f;
            #pragma unroll
            for (int c = 0; c < 5; c++) s += expf(lg[c] - mx);
            float lse = mx + logf(s);
            int gold = golden[e0 + r];
            lsum += (double)(lse - lg[gold]);
        }
    }
    if (lane == 0) atomicAdd(&g_acc, lsum);
}

// ---------------- finalize ----------------
__global__ void finalize_kernel(float* __restrict__ out, int esel)
{
    out[0] = (float)(g_acc / (double)esel);
}

// ---------------- host launcher (dual-stream fork/join, graph-capturable) ------------
extern "C" void kernel_launch(void* const* d_in, const int* in_sizes, int n_in,
                              void* d_out, int out_size)
{
    const float* x         = (const float*)d_in[0];
    const int*   eidx      = (const int*)  d_in[1];
    const float* edge_attr = (const float*)d_in[2];
    const float* props     = (const float*)d_in[3];
    const int*   sel_b     = (const int*)  d_in[4];
    const int*   sel_i     = (const int*)  d_in[5];
    const int*   sel_j     = (const int*)  d_in[6];
    const int*   golden    = (const int*)  d_in[7];
    const float* W_prop = (const float*)d_in[8];
    const float* b_prop = (const float*)d_in[9];
    const float* W_in   = (const float*)d_in[10];
    const float* b_in   = (const float*)d_in[11];
    const float* W_msg  = (const float*)d_in[12];
    const float* b_msg  = (const float*)d_in[13];
    const float* W_upd  = (const float*)d_in[14];
    const float* b_upd  = (const float*)d_in[15];
    const float* W_add  = (const float*)d_in[16];
    const float* b_add  = (const float*)d_in[17];
    const float* W1     = (const float*)d_in[18];
    const float* b1     = (const float*)d_in[19];
    const float* W2     = (const float*)d_in[20];
    const float* b2     = (const float*)d_in[21];
    const float* W3     = (const float*)d_in[22];
    const float* b3     = (const float*)d_in[23];
    const float* W_out  = (const float*)d_in[24];
    const float* b_out  = (const float*)d_in[25];

    int E    = in_sizes[1] / 2;
    int ESEL = in_sizes[4];
    const int* src = eidx;
    const int* dst = eidx + E;

    float *p_h, *p_ht, *p_agg, *p_A, *p_B, *p_Hm, *p_P, *p_Wr, *p_WAB, *p_pa, *p_pb;
    __nv_bfloat16* p_W2T;
    cudaGetSymbolAddress((void**)&p_h,    g_h);
    cudaGetSymbolAddress((void**)&p_ht,   g_ht);
    cudaGetSymbolAddress((void**)&p_agg,  g_agg);
    cudaGetSymbolAddress((void**)&p_A,    g_A);
    cudaGetSymbolAddress((void**)&p_B,    g_B);
    cudaGetSymbolAddress((void**)&p_Hm,   g_Hm);
    cudaGetSymbolAddress((void**)&p_P,    g_P);
    cudaGetSymbolAddress((void**)&p_Wr,   g_Wr);
    cudaGetSymbolAddress((void**)&p_WAB,  g_WAB);
    cudaGetSymbolAddress((void**)&p_pa,   g_pa);
    cudaGetSymbolAddress((void**)&p_pb,   g_pb);
    cudaGetSymbolAddress((void**)&p_W2T,  g_W2T);

    int gemmSmem = (2*64*APAD + 2*64*WPAD) * (int)sizeof(float);
    cudaFuncSetAttribute((const void*)sgemm_tc<0>, cudaFuncAttributeMaxDynamicSharedMemorySize, gemmSmem);
    cudaFuncSetAttribute((const void*)sgemm_tc<1>, cudaFuncAttributeMaxDynamicSharedMemorySize, gemmSmem);
    int pairSmem = (128*H1W + 2*256*WCH + 5*256 + 256 + 8) * (int)sizeof(uint32_t);
    cudaFuncSetAttribute(pair_kernel, cudaFuncAttributeMaxDynamicSharedMemorySize, pairSmem);

    dim3 gemmGrid(4, BNODES/64);

    const float* Wr_in   = p_Wr + OFF_IN;
    const float* Wr_msg  = p_Wr + OFF_MSG;
    const float* Wr_updT = p_Wr + OFF_UPD;
    const float* Wr_updB = p_Wr + OFF_UPD + 256*256;
    const float* WA_r    = p_WAB;
    const float* WB_r    = p_WAB + 65536;

    // side stream + fork/join events (graph-capture fork pattern)
    cudaStream_t s2;
    cudaStreamCreateWithFlags(&s2, cudaStreamNonBlocking);
    cudaEvent_t evF[5], evJ[5];
    for (int i = 0; i < 5; i++) {
        cudaEventCreateWithFlags(&evF[i], cudaEventDisableTiming);
        cudaEventCreateWithFlags(&evJ[i], cudaEventDisableTiming);
    }

    // ---- one-time setup ----
    setup_kernel<<<W2T_BLK0 + 64, 256>>>(W3, b3, W_out, b_out, props, W_prop, b_prop,
                                         W_add, b_add, b1, W_in, W_msg, W_upd, W1, W2);

    // h0 = relu(x @ W_in + b_in), rounded (x unrounded -> CVTA=1)
    sgemm_tc<1><<<gemmGrid, 256, gemmSmem>>>(x, Wr_in, 192, b_in, nullptr, p_h, 1, 1,
                                             nullptr, nullptr);

    float* cur = p_h;
    float* nxt = p_ht;
    for (int t = 0; t < 4; t++) {
        // fork: side stream computes P = cur@W_upd_top + b_upd (fp32, no round)
        cudaEventRecord(evF[t], 0);
        cudaStreamWaitEvent(s2, evF[t], 0);
        sgemm_tc<0><<<gemmGrid, 256, gemmSmem, s2>>>(cur, Wr_updT, 256, b_upd, nullptr,
                                                     p_P, 0, 0, nullptr, nullptr);
        cudaEventRecord(evJ[t], s2);

        // main: Hm = round(cur@W_msg), zeroes agg; then scatter
        sgemm_tc<0><<<gemmGrid, 256, gemmSmem>>>(cur, Wr_msg, 256, nullptr, nullptr,
                                                 p_Hm, 0, 1, p_agg, nullptr);
        edge_scatter<<<(E + 31)/32, 256>>>(src, dst, edge_attr, W_msg, b_msg, p_Hm, p_agg, E);

        // join, then h' = relu(round(agg)@W_upd_bot + P), rounded
        cudaStreamWaitEvent(0, evJ[t], 0);
        sgemm_tc<1><<<gemmGrid, 256, gemmSmem>>>(p_agg, Wr_updB, 256, nullptr, nullptr,
                                                 nxt, 1, 1, nullptr, p_P);
        float* tmp = cur; cur = nxt; nxt = tmp;
    }

    // fork A/B: B = h@WB + pb on s2, A = h@WA + pa on main
    cudaEventRecord(evF[4], 0);
    cudaStreamWaitEvent(s2, evF[4], 0);
    sgemm_tc<0><<<gemmGrid, 256, gemmSmem, s2>>>(cur, WB_r, 256, nullptr, p_pb,
                                                 p_B, 0, 0, nullptr, nullptr);
    cudaEventRecord(evJ[4], s2);
    sgemm_tc<0><<<gemmGrid, 256, gemmSmem>>>(cur, WA_r, 256, nullptr, p_pa,
                                             p_A, 0, 0, nullptr, nullptr);
    cudaStreamWaitEvent(0, evJ[4], 0);

    // pair stage + loss (bf16 MMA)
    pair_kernel<<<ESEL/128, 512, pairSmem>>>(p_A, p_B, sel_b, sel_i, sel_j, golden, p_W2T, b2);

    finalize_kernel<<<1, 1>>>((float*)d_out, ESEL);

    for (int i = 0; i < 5; i++) { cudaEventDestroy(evF[i]); cudaEventDestroy(evJ[i]); }
    cudaStreamDestroy(s2);
}